// round 1
// baseline (speedup 1.0000x reference)
#include <cuda_runtime.h>
#include <cstdint>
#include <cstdio>

#define D 128
#define BM 64
#define NT 256
#define NVMAX 100000
#define NCMAX 400000

// ---------------- scratch (device globals: allocation-free rule) ----------------
__device__ float g_apos[(size_t)NCMAX * D];
__device__ float g_aneg[(size_t)NCMAX * D];
__device__ float g_bpos[(size_t)NVMAX * D];
__device__ float g_bneg[(size_t)NVMAX * D];
__device__ float g_mv[(size_t)NVMAX * D];
__device__ float g_mc[(size_t)NCMAX * D];

// ---------------- fused 2-layer MLP:  Y = relu(relu(X@W1+b1)@W2+b2) ----------------
// X row = [Xa_row (128) | Xb_row (128 if KIN==256)]
// Block: 256 threads = 8 warps. Warp w owns rows w*8..w*8+7; lane owns cols lane*4..lane*4+3.
template<int KIN>
__global__ void __launch_bounds__(NT, 1) mlp2_kernel(
    const float* __restrict__ Xa, const float* __restrict__ Xb,
    const float* __restrict__ W1, const float* __restrict__ b1,
    const float* __restrict__ W2, const float* __restrict__ b2,
    float* __restrict__ Y, int N)
{
    constexpr int XROW = KIN + 4;   // pad to dodge bank conflicts; (KIN+4)*4B is 16B-multiple
    constexpr int HROW = D + 4;

    extern __shared__ float smem[];
    float* Xs = smem;                       // BM * XROW
    float* Ws = Xs + BM * XROW;             // D * D
    float* Hs = Ws + D * D;                 // BM * HROW

    const int tid  = threadIdx.x;
    const int lane = tid & 31;
    const int warp = tid >> 5;
    const int row0 = blockIdx.x * BM;

    // ---- load X tile (coalesced float4) ----
    {
        const int nv = BM * (KIN / 4);
        for (int i = tid; i < nv; i += NT) {
            int r  = i / (KIN / 4);
            int c  = i % (KIN / 4);
            int gr = row0 + r;
            float4 v = make_float4(0.f, 0.f, 0.f, 0.f);
            if (gr < N) {
                if (KIN == 128) {
                    v = ((const float4*)(Xa + (size_t)gr * 128))[c];
                } else {
                    if (c < 32) v = ((const float4*)(Xa + (size_t)gr * 128))[c];
                    else        v = ((const float4*)(Xb + (size_t)gr * 128))[c - 32];
                }
            }
            *(float4*)&Xs[r * XROW + c * 4] = v;
        }
    }

    // ---- layer 1 ----
    float acc[8][4];
    #pragma unroll
    for (int m = 0; m < 8; m++)
        #pragma unroll
        for (int n = 0; n < 4; n++) acc[m][n] = 0.f;

    for (int kc = 0; kc < KIN; kc += D) {
        __syncthreads();  // Xs ready (kc==0) / previous Ws consumers done (kc>0)
        for (int i = tid; i < D * D / 4; i += NT) {
            int r = i >> 5, c = i & 31;
            *(float4*)&Ws[r * D + c * 4] = ((const float4*)(W1 + (size_t)(kc + r) * D))[c];
        }
        __syncthreads();
        #pragma unroll 8
        for (int k = 0; k < D; k++) {
            float4 b = *(const float4*)&Ws[k * D + lane * 4];
            #pragma unroll
            for (int m = 0; m < 8; m++) {
                float a = Xs[(warp * 8 + m) * XROW + kc + k];
                acc[m][0] += a * b.x; acc[m][1] += a * b.y;
                acc[m][2] += a * b.z; acc[m][3] += a * b.w;
            }
        }
    }
    {
        float4 bb = *(const float4*)&b1[lane * 4];
        #pragma unroll
        for (int m = 0; m < 8; m++) {
            float4 h;
            h.x = fmaxf(acc[m][0] + bb.x, 0.f);
            h.y = fmaxf(acc[m][1] + bb.y, 0.f);
            h.z = fmaxf(acc[m][2] + bb.z, 0.f);
            h.w = fmaxf(acc[m][3] + bb.w, 0.f);
            *(float4*)&Hs[(warp * 8 + m) * HROW + lane * 4] = h;
        }
    }
    __syncthreads();  // Hs written, layer-1 Ws reads done

    // ---- layer 2 ----
    for (int i = tid; i < D * D / 4; i += NT) {
        int r = i >> 5, c = i & 31;
        *(float4*)&Ws[r * D + c * 4] = ((const float4*)(W2 + (size_t)r * D))[c];
    }
    __syncthreads();

    float acc2[8][4];
    #pragma unroll
    for (int m = 0; m < 8; m++)
        #pragma unroll
        for (int n = 0; n < 4; n++) acc2[m][n] = 0.f;

    #pragma unroll 8
    for (int k = 0; k < D; k++) {
        float4 b = *(const float4*)&Ws[k * D + lane * 4];
        #pragma unroll
        for (int m = 0; m < 8; m++) {
            float a = Hs[(warp * 8 + m) * HROW + k];
            acc2[m][0] += a * b.x; acc2[m][1] += a * b.y;
            acc2[m][2] += a * b.z; acc2[m][3] += a * b.w;
        }
    }
    {
        float4 bb = *(const float4*)&b2[lane * 4];
        #pragma unroll
        for (int m = 0; m < 8; m++) {
            int gr = row0 + warp * 8 + m;
            if (gr < N) {
                float4 o;
                o.x = fmaxf(acc2[m][0] + bb.x, 0.f);
                o.y = fmaxf(acc2[m][1] + bb.y, 0.f);
                o.z = fmaxf(acc2[m][2] + bb.z, 0.f);
                o.w = fmaxf(acc2[m][3] + bb.w, 0.f);
                *(float4*)(Y + (size_t)gr * D + lane * 4) = o;
            }
        }
    }
}

// ---------------- zero fill ----------------
__global__ void zero_kernel(float4* __restrict__ p, int n4)
{
    int i = blockIdx.x * blockDim.x + threadIdx.x;
    if (i < n4) p[i] = make_float4(0.f, 0.f, 0.f, 0.f);
}

// ---------------- edge scatter-add: dst[didx[e]] += src[sidx[e]]  (rows of 128 f32) ----------------
__global__ void scatter_kernel(const float* __restrict__ src, const int* __restrict__ sidx,
                               const int* __restrict__ didx, float* __restrict__ dst, int E)
{
    int g    = blockIdx.x * blockDim.x + threadIdx.x;
    int e    = g >> 5;
    int lane = g & 31;
    if (e >= E) return;
    int si = __ldg(&sidx[e]);
    int di = __ldg(&didx[e]);
    float4 v = ((const float4*)(src + (size_t)si * D))[lane];
    float* d = dst + (size_t)di * D + lane * 4;
    asm volatile("red.global.add.v4.f32 [%0], {%1,%2,%3,%4};"
                 :: "l"(d), "f"(v.x), "f"(v.y), "f"(v.z), "f"(v.w) : "memory");
}

// ---------------- launch ----------------
extern "C" void kernel_launch(void* const* d_in, const int* in_sizes, int n_in,
                              void* d_out, int out_size)
{
    const float* hv = (const float*)d_in[0];
    const float* hc = (const float*)d_in[1];
    // param blocks: [W1,b1,W2,b2] x {fmv_pos, fmv_neg, fmc_pos, fmc_neg, fuv, fuc} at d_in[2..25]
    const float* const* P = (const float* const*)(d_in + 2);
    const float* mvpW1 = P[0];  const float* mvpB1 = P[1];  const float* mvpW2 = P[2];  const float* mvpB2 = P[3];
    const float* mvnW1 = P[4];  const float* mvnB1 = P[5];  const float* mvnW2 = P[6];  const float* mvnB2 = P[7];
    const float* mcpW1 = P[8];  const float* mcpB1 = P[9];  const float* mcpW2 = P[10]; const float* mcpB2 = P[11];
    const float* mcnW1 = P[12]; const float* mcnB1 = P[13]; const float* mcnW2 = P[14]; const float* mcnB2 = P[15];
    const float* fuvW1 = P[16]; const float* fuvB1 = P[17]; const float* fuvW2 = P[18]; const float* fuvB2 = P[19];
    const float* fucW1 = P[20]; const float* fucB1 = P[21]; const float* fucW2 = P[22]; const float* fucB2 = P[23];
    const int* pos_v = (const int*)d_in[26];
    const int* pos_c = (const int*)d_in[27];
    const int* neg_v = (const int*)d_in[28];
    const int* neg_c = (const int*)d_in[29];
    float* out = (float*)d_out;

    const int NV = in_sizes[0] / D;
    const int NC = in_sizes[1] / D;
    const int EP = in_sizes[26];
    const int EN = in_sizes[28];

    float *apos, *aneg, *bpos, *bneg, *mv, *mc;
    cudaGetSymbolAddress((void**)&apos, g_apos);
    cudaGetSymbolAddress((void**)&aneg, g_aneg);
    cudaGetSymbolAddress((void**)&bpos, g_bpos);
    cudaGetSymbolAddress((void**)&bneg, g_bneg);
    cudaGetSymbolAddress((void**)&mv,   g_mv);
    cudaGetSymbolAddress((void**)&mc,   g_mc);

    const int SMEM128 = (BM * (128 + 4) + D * D + BM * (D + 4)) * 4;   // 133,120 B
    const int SMEM256 = (BM * (256 + 4) + D * D + BM * (D + 4)) * 4;   // 165,888 B
    cudaFuncSetAttribute(mlp2_kernel<128>, cudaFuncAttributeMaxDynamicSharedMemorySize, SMEM128);
    cudaFuncSetAttribute(mlp2_kernel<256>, cudaFuncAttributeMaxDynamicSharedMemorySize, SMEM256);

    const int grid_c = (NC + BM - 1) / BM;
    const int grid_v = (NV + BM - 1) / BM;

    // message MLPs
    mlp2_kernel<128><<<grid_c, NT, SMEM128>>>(hc, nullptr, mvpW1, mvpB1, mvpW2, mvpB2, apos, NC);
    mlp2_kernel<128><<<grid_c, NT, SMEM128>>>(hc, nullptr, mvnW1, mvnB1, mvnW2, mvnB2, aneg, NC);
    mlp2_kernel<128><<<grid_v, NT, SMEM128>>>(hv, nullptr, mcpW1, mcpB1, mcpW2, mcpB2, bpos, NV);
    mlp2_kernel<128><<<grid_v, NT, SMEM128>>>(hv, nullptr, mcnW1, mcnB1, mcnW2, mcnB2, bneg, NV);

    // zero accumulators
    {
        int n4v = NV * D / 4, n4c = NC * D / 4;
        zero_kernel<<<(n4v + 255) / 256, 256>>>((float4*)mv, n4v);
        zero_kernel<<<(n4c + 255) / 256, 256>>>((float4*)mc, n4c);
    }

    // edge scatter-adds
    scatter_kernel<<<(EP * 32 + 255) / 256, 256>>>(apos, pos_c, pos_v, mv, EP);
    scatter_kernel<<<(EN * 32 + 255) / 256, 256>>>(aneg, neg_c, neg_v, mv, EN);
    scatter_kernel<<<(EP * 32 + 255) / 256, 256>>>(bpos, pos_v, pos_c, mc, EP);
    scatter_kernel<<<(EN * 32 + 255) / 256, 256>>>(bneg, neg_v, neg_c, mc, EN);

    // update MLPs on concat([h, m])
    mlp2_kernel<256><<<grid_v, NT, SMEM256>>>(hv, mv, fuvW1, fuvB1, fuvW2, fuvB2, out, NV);
    mlp2_kernel<256><<<grid_c, NT, SMEM256>>>(hc, mc, fucW1, fucB1, fucW2, fucB2, out + (size_t)NV * D, NC);
}

// round 5
// speedup vs baseline: 1.7427x; 1.7427x over previous
#include <cuda_runtime.h>
#include <cstdint>

#define D 128
#define NVMAX 100000
#define NCMAX 400000

// ---------------- scratch (device globals: allocation-free rule) ----------------
__device__ float g_apos[(size_t)NCMAX * D];
__device__ float g_aneg[(size_t)NCMAX * D];
__device__ float g_bpos[(size_t)NVMAX * D];
__device__ float g_bneg[(size_t)NVMAX * D];
__device__ float g_mv[(size_t)NVMAX * D];
__device__ float g_mc[(size_t)NCMAX * D];

// ---------------- helpers ----------------
__device__ __forceinline__ uint32_t smem_u32(const void* p) {
    uint32_t a;
    asm("{ .reg .u64 t; cvta.to.shared.u64 t, %1; cvt.u32.u64 %0, t; }" : "=r"(a) : "l"(p));
    return a;
}
__device__ __forceinline__ float to_tf32(float x) {
    uint32_t u;
    asm("cvt.rna.tf32.f32 %0, %1;" : "=r"(u) : "f"(x));
    return __uint_as_float(u);
}

#define LDSM4(r0, r1, r2, r3, addr) \
    asm volatile("ldmatrix.sync.aligned.m8n8.x4.shared.b16 {%0,%1,%2,%3}, [%4];" \
                 : "=r"(r0), "=r"(r1), "=r"(r2), "=r"(r3) : "r"(addr))

__device__ __forceinline__ void mma_1688(float* c, const uint32_t* a, const uint32_t* b) {
    asm volatile(
        "mma.sync.aligned.m16n8k8.row.col.f32.tf32.tf32.f32 "
        "{%0,%1,%2,%3}, {%4,%5,%6,%7}, {%8,%9}, {%0,%1,%2,%3};"
        : "+f"(c[0]), "+f"(c[1]), "+f"(c[2]), "+f"(c[3])
        : "r"(a[0]), "r"(a[1]), "r"(a[2]), "r"(a[3]), "r"(b[0]), "r"(b[1]));
}

// ---------------- fused 2-layer MLP on mma.sync tf32 ----------------
// Y = relu(relu(X@W1+b1)@W2+b2);  X row = [Xa | Xb] if KIN==256
// CTA: 256 threads (8 warps), tile 128 rows x 128 cols, warp tile 32x64.
constexpr int XST = 132;   // smem row stride (floats); 528B: 16B-aligned, LDSM conflict-free

template<int KIN>
__global__ void __launch_bounds__(256, 1) mma_mlp2(
    const float* __restrict__ Xa, const float* __restrict__ Xb,
    const float* __restrict__ W1, const float* __restrict__ b1,
    const float* __restrict__ W2, const float* __restrict__ b2,
    float* __restrict__ Y, int N)
{
    extern __shared__ float smem[];
    float* Xs  = smem;                    // 128 * XST
    float* Ws  = smem + 128 * XST;        // 128 * XST (holds W^T chunk: [n][k])
    float* b1s = smem + 2 * 128 * XST;    // 128
    float* b2s = b1s + 128;               // 128

    const int tid   = threadIdx.x;
    const int lane  = tid & 31;
    const int warp  = tid >> 5;
    const int rbase = (warp & 3) * 32;    // warp row block
    const int nbase = (warp >> 2) * 64;   // warp col block
    const int row0  = blockIdx.x * 128;

    if (tid < 128) { b1s[tid] = b1[tid]; b2s[tid] = b2[tid]; }

    const uint32_t xs_u = smem_u32(Xs);
    const uint32_t ws_u = smem_u32(Ws);

    // per-lane ldmatrix row/col offsets (see fragment layouts of m16n8k8 tf32)
    const int a_r = ((lane >> 3) & 1) * 8 + (lane & 7);   // A: M0=a0,M1=a1(+8r),M2=a2(+4k),M3=a3
    const int a_c = (lane >> 4) * 4;
    const int b_r = (lane >> 4) * 8 + (lane & 7);         // B: M0=b0(nt),M1=b1(nt),M2=b0(nt+1),M3=b1(nt+1)
    const int b_c = ((lane >> 3) & 1) * 4;

    // ---- tile loaders (values stored pre-rounded to tf32) ----
    auto load_x = [&](const float* __restrict__ P) {
        for (int i = tid; i < 128 * 32; i += 256) {
            int r = i >> 5, c4 = i & 31;
            int gr = row0 + r;
            float4 v = make_float4(0.f, 0.f, 0.f, 0.f);
            if (gr < N) v = ((const float4*)(P + (size_t)gr * 128))[c4];
            v.x = to_tf32(v.x); v.y = to_tf32(v.y); v.z = to_tf32(v.z); v.w = to_tf32(v.w);
            *(float4*)&Xs[r * XST + c4 * 4] = v;
        }
    };
    auto load_w = [&](const float* __restrict__ W) {   // Ws[n][k] = W[k][n]
        for (int i = tid; i < 128 * 128; i += 256) {
            int k = i >> 7, n = i & 127;
            Ws[n * XST + k] = to_tf32(W[(size_t)k * 128 + n]);
        }
    };
    auto mma_layer = [&](float (*cc)[8][4]) {
        #pragma unroll 4
        for (int k0 = 0; k0 < 128; k0 += 8) {
            uint32_t a[2][4], b[4][4];
            #pragma unroll
            for (int mt = 0; mt < 2; mt++) {
                uint32_t ad = xs_u + (uint32_t)(((rbase + mt * 16 + a_r) * XST + k0 + a_c) << 2);
                LDSM4(a[mt][0], a[mt][1], a[mt][2], a[mt][3], ad);
            }
            #pragma unroll
            for (int np = 0; np < 4; np++) {
                uint32_t bd = ws_u + (uint32_t)(((nbase + np * 16 + b_r) * XST + k0 + b_c) << 2);
                LDSM4(b[np][0], b[np][1], b[np][2], b[np][3], bd);
            }
            #pragma unroll
            for (int mt = 0; mt < 2; mt++)
                #pragma unroll
                for (int nt = 0; nt < 8; nt++)
                    mma_1688(cc[mt][nt], a[mt], &b[nt >> 1][(nt & 1) * 2]);
        }
    };

    // ---- layer 1 ----
    float c1[2][8][4];
    #pragma unroll
    for (int mt = 0; mt < 2; mt++)
        #pragma unroll
        for (int nt = 0; nt < 8; nt++)
            #pragma unroll
            for (int j = 0; j < 4; j++) c1[mt][nt][j] = 0.f;

    load_x(Xa);
    load_w(W1);
    __syncthreads();
    mma_layer(c1);
    if constexpr (KIN == 256) {
        __syncthreads();
        load_x(Xb);                       // concat second half == Xb rows
        load_w(W1 + 128 * 128);           // K rows 128..255 of W1
        __syncthreads();
        mma_layer(c1);                    // accumulate
    }
    __syncthreads();                      // all reads of Xs/Ws done

    // ---- epilogue 1: H = relu(c1 + b1) -> Xs (tf32); stage W2^T ----
    {
        const int cr = lane >> 2, cc2 = 2 * (lane & 3);
        #pragma unroll
        for (int mt = 0; mt < 2; mt++)
            #pragma unroll
            for (int nt = 0; nt < 8; nt++) {
                int col = nbase + nt * 8 + cc2;
                int r0  = rbase + mt * 16 + cr;
                float2 h0, h1;
                h0.x = to_tf32(fmaxf(c1[mt][nt][0] + b1s[col],     0.f));
                h0.y = to_tf32(fmaxf(c1[mt][nt][1] + b1s[col + 1], 0.f));
                h1.x = to_tf32(fmaxf(c1[mt][nt][2] + b1s[col],     0.f));
                h1.y = to_tf32(fmaxf(c1[mt][nt][3] + b1s[col + 1], 0.f));
                *(float2*)&Xs[r0 * XST + col]       = h0;
                *(float2*)&Xs[(r0 + 8) * XST + col] = h1;
            }
    }
    load_w(W2);
    __syncthreads();

    // ---- layer 2 ----
    float c2[2][8][4];
    #pragma unroll
    for (int mt = 0; mt < 2; mt++)
        #pragma unroll
        for (int nt = 0; nt < 8; nt++)
            #pragma unroll
            for (int j = 0; j < 4; j++) c2[mt][nt][j] = 0.f;
    mma_layer(c2);

    // ---- epilogue 2: Y = relu(c2 + b2) ----
    {
        const int cr = lane >> 2, cc2 = 2 * (lane & 3);
        #pragma unroll
        for (int mt = 0; mt < 2; mt++)
            #pragma unroll
            for (int nt = 0; nt < 8; nt++) {
                int col = nbase + nt * 8 + cc2;
                int r0  = rbase + mt * 16 + cr;
                int g0  = row0 + r0, g1 = g0 + 8;
                if (g0 < N) {
                    float2 o;
                    o.x = fmaxf(c2[mt][nt][0] + b2s[col],     0.f);
                    o.y = fmaxf(c2[mt][nt][1] + b2s[col + 1], 0.f);
                    *(float2*)&Y[(size_t)g0 * 128 + col] = o;
                }
                if (g1 < N) {
                    float2 o;
                    o.x = fmaxf(c2[mt][nt][2] + b2s[col],     0.f);
                    o.y = fmaxf(c2[mt][nt][3] + b2s[col + 1], 0.f);
                    *(float2*)&Y[(size_t)g1 * 128 + col] = o;
                }
            }
    }
}

// ---------------- zero fill ----------------
__global__ void zero_kernel(float4* __restrict__ p, int n4)
{
    int i = blockIdx.x * blockDim.x + threadIdx.x;
    if (i < n4) p[i] = make_float4(0.f, 0.f, 0.f, 0.f);
}

// ---------------- edge scatter-add: dst[didx[e]] += src[sidx[e]]  (rows of 128 f32) ----------------
__global__ void scatter_kernel(const float* __restrict__ src, const int* __restrict__ sidx,
                               const int* __restrict__ didx, float* __restrict__ dst, int E)
{
    int g    = blockIdx.x * blockDim.x + threadIdx.x;
    int e    = g >> 5;
    int lane = g & 31;
    if (e >= E) return;
    int si = __ldg(&sidx[e]);
    int di = __ldg(&didx[e]);
    float4 v = ((const float4*)(src + (size_t)si * D))[lane];
    float* d = dst + (size_t)di * D + lane * 4;
    asm volatile("red.global.add.v4.f32 [%0], {%1,%2,%3,%4};"
                 :: "l"(d), "f"(v.x), "f"(v.y), "f"(v.z), "f"(v.w) : "memory");
}

// ---------------- launch ----------------
extern "C" void kernel_launch(void* const* d_in, const int* in_sizes, int n_in,
                              void* d_out, int out_size)
{
    const float* hv = (const float*)d_in[0];
    const float* hc = (const float*)d_in[1];
    const float* const* P = (const float* const*)(d_in + 2);
    const float* mvpW1 = P[0];  const float* mvpB1 = P[1];  const float* mvpW2 = P[2];  const float* mvpB2 = P[3];
    const float* mvnW1 = P[4];  const float* mvnB1 = P[5];  const float* mvnW2 = P[6];  const float* mvnB2 = P[7];
    const float* mcpW1 = P[8];  const float* mcpB1 = P[9];  const float* mcpW2 = P[10]; const float* mcpB2 = P[11];
    const float* mcnW1 = P[12]; const float* mcnB1 = P[13]; const float* mcnW2 = P[14]; const float* mcnB2 = P[15];
    const float* fuvW1 = P[16]; const float* fuvB1 = P[17]; const float* fuvW2 = P[18]; const float* fuvB2 = P[19];
    const float* fucW1 = P[20]; const float* fucB1 = P[21]; const float* fucW2 = P[22]; const float* fucB2 = P[23];
    const int* pos_v = (const int*)d_in[26];
    const int* pos_c = (const int*)d_in[27];
    const int* neg_v = (const int*)d_in[28];
    const int* neg_c = (const int*)d_in[29];
    float* out = (float*)d_out;

    const int NV = in_sizes[0] / D;
    const int NC = in_sizes[1] / D;
    const int EP = in_sizes[26];
    const int EN = in_sizes[28];

    float *apos, *aneg, *bpos, *bneg, *mv, *mc;
    cudaGetSymbolAddress((void**)&apos, g_apos);
    cudaGetSymbolAddress((void**)&aneg, g_aneg);
    cudaGetSymbolAddress((void**)&bpos, g_bpos);
    cudaGetSymbolAddress((void**)&bneg, g_bneg);
    cudaGetSymbolAddress((void**)&mv,   g_mv);
    cudaGetSymbolAddress((void**)&mc,   g_mc);

    const int SMEM = (2 * 128 * XST + 256) * 4;   // 136,192 B
    cudaFuncSetAttribute(mma_mlp2<128>, cudaFuncAttributeMaxDynamicSharedMemorySize, SMEM);
    cudaFuncSetAttribute(mma_mlp2<256>, cudaFuncAttributeMaxDynamicSharedMemorySize, SMEM);

    const int grid_c = (NC + 127) / 128;
    const int grid_v = (NV + 127) / 128;

    // message MLPs
    mma_mlp2<128><<<grid_c, 256, SMEM>>>(hc, nullptr, mvpW1, mvpB1, mvpW2, mvpB2, apos, NC);
    mma_mlp2<128><<<grid_c, 256, SMEM>>>(hc, nullptr, mvnW1, mvnB1, mvnW2, mvnB2, aneg, NC);
    mma_mlp2<128><<<grid_v, 256, SMEM>>>(hv, nullptr, mcpW1, mcpB1, mcpW2, mcpB2, bpos, NV);
    mma_mlp2<128><<<grid_v, 256, SMEM>>>(hv, nullptr, mcnW1, mcnB1, mcnW2, mcnB2, bneg, NV);

    // zero accumulators
    {
        int n4v = NV * D / 4, n4c = NC * D / 4;
        zero_kernel<<<(n4v + 255) / 256, 256>>>((float4*)mv, n4v);
        zero_kernel<<<(n4c + 255) / 256, 256>>>((float4*)mc, n4c);
    }

    // edge scatter-adds
    scatter_kernel<<<(EP * 32 + 255) / 256, 256>>>(apos, pos_c, pos_v, mv, EP);
    scatter_kernel<<<(EN * 32 + 255) / 256, 256>>>(aneg, neg_c, neg_v, mv, EN);
    scatter_kernel<<<(EP * 32 + 255) / 256, 256>>>(bpos, pos_v, pos_c, mc, EP);
    scatter_kernel<<<(EN * 32 + 255) / 256, 256>>>(bneg, neg_v, neg_c, mc, EN);

    // update MLPs on concat([h, m])
    mma_mlp2<256><<<grid_v, 256, SMEM>>>(hv, mv, fuvW1, fuvB1, fuvW2, fuvB2, out, NV);
    mma_mlp2<256><<<grid_c, 256, SMEM>>>(hc, mc, fucW1, fucB1, fucW2, fucB2, out + (size_t)NV * D, NC);
}

// round 6
// speedup vs baseline: 2.3855x; 1.3688x over previous
#include <cuda_runtime.h>
#include <cstdint>

#define D 128
#define NVMAX 100000
#define NCMAX 400000

// ---------------- scratch (device globals: allocation-free rule) ----------------
__device__ float g_apos[(size_t)NCMAX * D];
__device__ float g_aneg[(size_t)NCMAX * D];
__device__ float g_bpos[(size_t)NVMAX * D];
__device__ float g_bneg[(size_t)NVMAX * D];
__device__ float g_mv[(size_t)NVMAX * D];
__device__ float g_mc[(size_t)NCMAX * D];

// ---------------- helpers ----------------
__device__ __forceinline__ uint32_t smem_u32(const void* p) {
    uint32_t a;
    asm("{ .reg .u64 t; cvta.to.shared.u64 t, %1; cvt.u32.u64 %0, t; }" : "=r"(a) : "l"(p));
    return a;
}
__device__ __forceinline__ float to_tf32(float x) {
    uint32_t u;
    asm("cvt.rna.tf32.f32 %0, %1;" : "=r"(u) : "f"(x));
    return __uint_as_float(u);
}

#define LDSM4(r0, r1, r2, r3, addr) \
    asm volatile("ldmatrix.sync.aligned.m8n8.x4.shared.b16 {%0,%1,%2,%3}, [%4];" \
                 : "=r"(r0), "=r"(r1), "=r"(r2), "=r"(r3) : "r"(addr))

__device__ __forceinline__ void mma_1688(float* c, const uint32_t* a, const uint32_t* b) {
    asm volatile(
        "mma.sync.aligned.m16n8k8.row.col.f32.tf32.tf32.f32 "
        "{%0,%1,%2,%3}, {%4,%5,%6,%7}, {%8,%9}, {%0,%1,%2,%3};"
        : "+f"(c[0]), "+f"(c[1]), "+f"(c[2]), "+f"(c[3])
        : "r"(a[0]), "r"(a[1]), "r"(a[2]), "r"(a[3]), "r"(b[0]), "r"(b[1]));
}

// ---------------- fused 2-layer MLP on mma.sync tf32 ----------------
// Y = relu(relu(X@W1+b1)@W2+b2);  X row = [Xa | Xb] if KIN==256
// CTA: 256 threads (8 warps), tile 128 rows x 128 cols.
// N processed in two 64-wide halves streaming W^T (64x128) -> smem 102.4KB -> 2 CTAs/SM.
// Warp tile per half: 32 rows x 32 cols  (warp grid 4 x 2).
constexpr int XST = 132;   // smem row stride (floats); 528B: 16B-aligned, LDSM conflict-free

template<int KIN>
__global__ void __launch_bounds__(256, 2) mma_mlp2(
    const float* __restrict__ Xa, const float* __restrict__ Xb,
    const float* __restrict__ W1, const float* __restrict__ b1,
    const float* __restrict__ W2, const float* __restrict__ b2,
    float* __restrict__ Y, int N)
{
    extern __shared__ float smem[];
    float* Xs  = smem;                          // 128 * XST
    float* Ws  = smem + 128 * XST;              // 64 * XST  (W^T half: [n][k])
    float* b1s = smem + 128 * XST + 64 * XST;   // 128
    float* b2s = b1s + 128;                     // 128

    const int tid   = threadIdx.x;
    const int lane  = tid & 31;
    const int warp  = tid >> 5;
    const int rbase = (warp & 3) * 32;          // warp row block
    const int nbh   = (warp >> 2) * 32;         // warp col block within 64-wide half
    const int row0  = blockIdx.x * 128;

    if (tid < 128) { b1s[tid] = b1[tid]; b2s[tid] = b2[tid]; }

    const uint32_t xs_u = smem_u32(Xs);
    const uint32_t ws_u = smem_u32(Ws);

    // per-lane ldmatrix row/col offsets (m16n8k8 tf32 fragment layouts)
    const int a_r = ((lane >> 3) & 1) * 8 + (lane & 7);
    const int a_c = (lane >> 4) * 4;
    const int b_r = (lane >> 4) * 8 + (lane & 7);
    const int b_c = ((lane >> 3) & 1) * 4;

    auto load_x = [&](const float* __restrict__ P) {
        for (int i = tid; i < 128 * 32; i += 256) {
            int r = i >> 5, c4 = i & 31;
            int gr = row0 + r;
            float4 v = make_float4(0.f, 0.f, 0.f, 0.f);
            if (gr < N) v = ((const float4*)(P + (size_t)gr * 128))[c4];
            v.x = to_tf32(v.x); v.y = to_tf32(v.y); v.z = to_tf32(v.z); v.w = to_tf32(v.w);
            *(float4*)&Xs[r * XST + c4 * 4] = v;
        }
    };
    // Ws[n][k] = W[k][nh*64+n], n in [0,64)
    auto load_w = [&](const float* __restrict__ W, int nh) {
        const float* Wb = W + nh * 64;
        for (int i = tid; i < 64 * 128; i += 256) {
            int k = i >> 6, n = i & 63;
            Ws[n * XST + k] = to_tf32(Wb[(size_t)k * 128 + n]);
        }
    };
    // one half: 128-K MMA pass into cc[mt][nt]  (mt:2 x 16 rows, nt:4 x 8 cols)
    auto mma_half = [&](float (*cc)[4][4]) {
        #pragma unroll 4
        for (int k0 = 0; k0 < 128; k0 += 8) {
            uint32_t a[2][4], b[2][4];
            #pragma unroll
            for (int mt = 0; mt < 2; mt++) {
                uint32_t ad = xs_u + (uint32_t)(((rbase + mt * 16 + a_r) * XST + k0 + a_c) << 2);
                LDSM4(a[mt][0], a[mt][1], a[mt][2], a[mt][3], ad);
            }
            #pragma unroll
            for (int np = 0; np < 2; np++) {
                uint32_t bd = ws_u + (uint32_t)(((nbh + np * 16 + b_r) * XST + k0 + b_c) << 2);
                LDSM4(b[np][0], b[np][1], b[np][2], b[np][3], bd);
            }
            #pragma unroll
            for (int mt = 0; mt < 2; mt++)
                #pragma unroll
                for (int nt = 0; nt < 4; nt++)
                    mma_1688(cc[mt][nt], a[mt], &b[nt >> 1][(nt & 1) * 2]);
        }
    };
    auto zero_acc = [&](float (*cc)[2][4][4]) {
        #pragma unroll
        for (int h = 0; h < 2; h++)
            #pragma unroll
            for (int mt = 0; mt < 2; mt++)
                #pragma unroll
                for (int nt = 0; nt < 4; nt++)
                    #pragma unroll
                    for (int j = 0; j < 4; j++) cc[h][mt][nt][j] = 0.f;
    };

    // ---- layer 1 ----
    float c1[2][2][4][4];
    zero_acc(c1);

    load_x(Xa);
    load_w(W1, 0);
    __syncthreads();
    mma_half(c1[0]);
    __syncthreads();
    load_w(W1, 1);
    __syncthreads();
    mma_half(c1[1]);
    if constexpr (KIN == 256) {
        __syncthreads();
        load_x(Xb);                        // concat second half == Xb rows
        load_w(W1 + 128 * 128, 0);         // K rows 128..255 of W1
        __syncthreads();
        mma_half(c1[0]);
        __syncthreads();
        load_w(W1 + 128 * 128, 1);
        __syncthreads();
        mma_half(c1[1]);
    }
    __syncthreads();                       // all reads of Xs/Ws done

    // ---- epilogue 1: H = relu(c1 + b1) -> Xs (tf32); stage W2^T half 0 ----
    {
        const int cr = lane >> 2, cc2 = 2 * (lane & 3);
        #pragma unroll
        for (int h = 0; h < 2; h++)
            #pragma unroll
            for (int mt = 0; mt < 2; mt++)
                #pragma unroll
                for (int nt = 0; nt < 4; nt++) {
                    int col = h * 64 + nbh + nt * 8 + cc2;
                    int r0  = rbase + mt * 16 + cr;
                    float2 h0, h1;
                    h0.x = to_tf32(fmaxf(c1[h][mt][nt][0] + b1s[col],     0.f));
                    h0.y = to_tf32(fmaxf(c1[h][mt][nt][1] + b1s[col + 1], 0.f));
                    h1.x = to_tf32(fmaxf(c1[h][mt][nt][2] + b1s[col],     0.f));
                    h1.y = to_tf32(fmaxf(c1[h][mt][nt][3] + b1s[col + 1], 0.f));
                    *(float2*)&Xs[r0 * XST + col]       = h0;
                    *(float2*)&Xs[(r0 + 8) * XST + col] = h1;
                }
    }
    load_w(W2, 0);
    __syncthreads();

    // ---- layer 2 ----
    float c2[2][2][4][4];
    zero_acc(c2);
    mma_half(c2[0]);
    __syncthreads();
    load_w(W2, 1);
    __syncthreads();
    mma_half(c2[1]);

    // ---- epilogue 2: Y = relu(c2 + b2) ----
    {
        const int cr = lane >> 2, cc2 = 2 * (lane & 3);
        #pragma unroll
        for (int h = 0; h < 2; h++)
            #pragma unroll
            for (int mt = 0; mt < 2; mt++)
                #pragma unroll
                for (int nt = 0; nt < 4; nt++) {
                    int col = h * 64 + nbh + nt * 8 + cc2;
                    int r0  = rbase + mt * 16 + cr;
                    int g0  = row0 + r0, g1 = g0 + 8;
                    if (g0 < N) {
                        float2 o;
                        o.x = fmaxf(c2[h][mt][nt][0] + b2s[col],     0.f);
                        o.y = fmaxf(c2[h][mt][nt][1] + b2s[col + 1], 0.f);
                        *(float2*)&Y[(size_t)g0 * 128 + col] = o;
                    }
                    if (g1 < N) {
                        float2 o;
                        o.x = fmaxf(c2[h][mt][nt][2] + b2s[col],     0.f);
                        o.y = fmaxf(c2[h][mt][nt][3] + b2s[col + 1], 0.f);
                        *(float2*)&Y[(size_t)g1 * 128 + col] = o;
                    }
                }
    }
}

// ---------------- zero fill ----------------
__global__ void zero_kernel(float4* __restrict__ p, int n4)
{
    int i = blockIdx.x * blockDim.x + threadIdx.x;
    if (i < n4) p[i] = make_float4(0.f, 0.f, 0.f, 0.f);
}

// ---------------- edge scatter-add: dst[didx[e]] += src[sidx[e]]  (rows of 128 f32) ----------------
__global__ void scatter_kernel(const float* __restrict__ src, const int* __restrict__ sidx,
                               const int* __restrict__ didx, float* __restrict__ dst, int E)
{
    int g    = blockIdx.x * blockDim.x + threadIdx.x;
    int e    = g >> 5;
    int lane = g & 31;
    if (e >= E) return;
    int si = __ldg(&sidx[e]);
    int di = __ldg(&didx[e]);
    float4 v = ((const float4*)(src + (size_t)si * D))[lane];
    float* d = dst + (size_t)di * D + lane * 4;
    asm volatile("red.global.add.v4.f32 [%0], {%1,%2,%3,%4};"
                 :: "l"(d), "f"(v.x), "f"(v.y), "f"(v.z), "f"(v.w) : "memory");
}

// ---------------- launch ----------------
extern "C" void kernel_launch(void* const* d_in, const int* in_sizes, int n_in,
                              void* d_out, int out_size)
{
    const float* hv = (const float*)d_in[0];
    const float* hc = (const float*)d_in[1];
    const float* const* P = (const float* const*)(d_in + 2);
    const float* mvpW1 = P[0];  const float* mvpB1 = P[1];  const float* mvpW2 = P[2];  const float* mvpB2 = P[3];
    const float* mvnW1 = P[4];  const float* mvnB1 = P[5];  const float* mvnW2 = P[6];  const float* mvnB2 = P[7];
    const float* mcpW1 = P[8];  const float* mcpB1 = P[9];  const float* mcpW2 = P[10]; const float* mcpB2 = P[11];
    const float* mcnW1 = P[12]; const float* mcnB1 = P[13]; const float* mcnW2 = P[14]; const float* mcnB2 = P[15];
    const float* fuvW1 = P[16]; const float* fuvB1 = P[17]; const float* fuvW2 = P[18]; const float* fuvB2 = P[19];
    const float* fucW1 = P[20]; const float* fucB1 = P[21]; const float* fucW2 = P[22]; const float* fucB2 = P[23];
    const int* pos_v = (const int*)d_in[26];
    const int* pos_c = (const int*)d_in[27];
    const int* neg_v = (const int*)d_in[28];
    const int* neg_c = (const int*)d_in[29];
    float* out = (float*)d_out;

    const int NV = in_sizes[0] / D;
    const int NC = in_sizes[1] / D;
    const int EP = in_sizes[26];
    const int EN = in_sizes[28];

    float *apos, *aneg, *bpos, *bneg, *mv, *mc;
    cudaGetSymbolAddress((void**)&apos, g_apos);
    cudaGetSymbolAddress((void**)&aneg, g_aneg);
    cudaGetSymbolAddress((void**)&bpos, g_bpos);
    cudaGetSymbolAddress((void**)&bneg, g_bneg);
    cudaGetSymbolAddress((void**)&mv,   g_mv);
    cudaGetSymbolAddress((void**)&mc,   g_mc);

    const int SMEM = (128 * XST + 64 * XST + 256) * 4;   // 102,400 B -> 2 CTAs/SM
    cudaFuncSetAttribute(mma_mlp2<128>, cudaFuncAttributeMaxDynamicSharedMemorySize, SMEM);
    cudaFuncSetAttribute(mma_mlp2<256>, cudaFuncAttributeMaxDynamicSharedMemorySize, SMEM);

    const int grid_c = (NC + 127) / 128;
    const int grid_v = (NV + 127) / 128;

    // message MLPs
    mma_mlp2<128><<<grid_c, 256, SMEM>>>(hc, nullptr, mvpW1, mvpB1, mvpW2, mvpB2, apos, NC);
    mma_mlp2<128><<<grid_c, 256, SMEM>>>(hc, nullptr, mvnW1, mvnB1, mvnW2, mvnB2, aneg, NC);
    mma_mlp2<128><<<grid_v, 256, SMEM>>>(hv, nullptr, mcpW1, mcpB1, mcpW2, mcpB2, bpos, NV);
    mma_mlp2<128><<<grid_v, 256, SMEM>>>(hv, nullptr, mcnW1, mcnB1, mcnW2, mcnB2, bneg, NV);

    // zero accumulators
    {
        int n4v = NV * D / 4, n4c = NC * D / 4;
        zero_kernel<<<(n4v + 255) / 256, 256>>>((float4*)mv, n4v);
        zero_kernel<<<(n4c + 255) / 256, 256>>>((float4*)mc, n4c);
    }

    // edge scatter-adds
    scatter_kernel<<<(EP * 32 + 255) / 256, 256>>>(apos, pos_c, pos_v, mv, EP);
    scatter_kernel<<<(EN * 32 + 255) / 256, 256>>>(aneg, neg_c, neg_v, mv, EN);
    scatter_kernel<<<(EP * 32 + 255) / 256, 256>>>(bpos, pos_v, pos_c, mc, EP);
    scatter_kernel<<<(EN * 32 + 255) / 256, 256>>>(bneg, neg_v, neg_c, mc, EN);

    // update MLPs on concat([h, m])
    mma_mlp2<256><<<grid_v, 256, SMEM>>>(hv, mv, fuvW1, fuvB1, fuvW2, fuvB2, out, NV);
    mma_mlp2<256><<<grid_c, 256, SMEM>>>(hc, mc, fucW1, fucB1, fucW2, fucB2, out + (size_t)NV * D, NC);
}